// round 2
// baseline (speedup 1.0000x reference)
#include <cuda_runtime.h>
#include <cuda_bf16.h>
#include <math.h>

#define D_MODEL   1024
#define MEM_SIZE  131072
#define TOP_K     64
#define D_STATE   16
#define D_CONV    4
#define D_INNER   2048
#define DT_RANK   64
#define XPROJ_OUT (DT_RANK + 2*D_STATE)   // 96
#define L_SEQ     64
#define EPS_COS   1e-8f
#define EPS_LN    1e-5f

// ---------------- scratch (no allocations allowed) ----------------
__device__ float g_sims[MEM_SIZE];
__device__ float g_cand_val[4096];
__device__ int   g_cand_idx[4096];
__device__ int   g_topk[TOP_K];
__device__ float g_qn[1];
__device__ float g_xz[L_SEQ * 2 * D_INNER];     // 64 x 4096
__device__ float g_uact[L_SEQ * D_INNER];       // 64 x 2048 (post conv+silu)
__device__ float g_xdbl[L_SEQ * XPROJ_OUT];     // 64 x 96
__device__ float g_delta[L_SEQ * D_INNER];      // 64 x 2048
__device__ float g_y[D_INNER];                  // gated y at t=63
__device__ float g_ctx[D_MODEL];                // out_proj result

// ---------------- query norm ----------------
__global__ void k_qnorm(const float* __restrict__ q) {
    __shared__ float red[256];
    int t = threadIdx.x;
    float s = 0.f;
    for (int i = t; i < D_MODEL; i += 256) { float v = q[i]; s += v*v; }
    red[t] = s; __syncthreads();
    for (int o = 128; o > 0; o >>= 1) { if (t < o) red[t] += red[t+o]; __syncthreads(); }
    if (t == 0) g_qn[0] = sqrtf(red[0]);
}

// ---------------- fused dot + norm + cosine sim ----------------
__global__ void k_sims(const float* __restrict__ mem, const float* __restrict__ q) {
    __shared__ float sq[D_MODEL];
    int t = threadIdx.x;
    for (int i = t; i < D_MODEL; i += 256) sq[i] = q[i];
    __syncthreads();
    int warp = t >> 5, lane = t & 31;
    float qn = g_qn[0];
    int rbase = blockIdx.x * 128 + warp * 16;
    for (int rr = 0; rr < 16; rr++) {
        int r = rbase + rr;
        const float4* row = (const float4*)(mem + (size_t)r * D_MODEL);
        float dot = 0.f, nr = 0.f;
        #pragma unroll
        for (int i = 0; i < 8; i++) {
            int j = i * 32 + lane;
            float4 m = row[j];
            float4 qv = *(const float4*)&sq[j*4];
            dot += m.x*qv.x + m.y*qv.y + m.z*qv.z + m.w*qv.w;
            nr  += m.x*m.x + m.y*m.y + m.z*m.z + m.w*m.w;
        }
        #pragma unroll
        for (int o = 16; o > 0; o >>= 1) {
            dot += __shfl_xor_sync(0xffffffffu, dot, o);
            nr  += __shfl_xor_sync(0xffffffffu, nr,  o);
        }
        if (lane == 0)
            g_sims[r] = dot / fmaxf(sqrtf(nr) * qn, EPS_COS);
    }
}

// ---------------- top-k stage 1: per-block bitonic sort of 2048 ----------------
__device__ __forceinline__ bool before_pair(float va, int ia, float vb, int ib) {
    return (va > vb) || (va == vb && ia < ib);   // value desc, index asc
}

__global__ void k_top1() {
    __shared__ float sv[2048];
    __shared__ int   si[2048];
    int t = threadIdx.x;
    int base = blockIdx.x * 2048;
    sv[t]        = g_sims[base + t];        si[t]        = base + t;
    sv[t + 1024] = g_sims[base + t + 1024]; si[t + 1024] = base + t + 1024;
    __syncthreads();
    for (int k = 2; k <= 2048; k <<= 1) {
        for (int j = k >> 1; j > 0; j >>= 1) {
            for (int i = t; i < 2048; i += 1024) {
                int ixj = i ^ j;
                if (ixj > i) {
                    bool up = ((i & k) == 0);
                    float va = sv[i], vb = sv[ixj];
                    int ia = si[i], ib = si[ixj];
                    bool bba = before_pair(vb, ib, va, ia);
                    if (bba == up) { sv[i]=vb; sv[ixj]=va; si[i]=ib; si[ixj]=ia; }
                }
            }
            __syncthreads();
        }
    }
    if (t < 64) { g_cand_val[blockIdx.x*64 + t] = sv[t]; g_cand_idx[blockIdx.x*64 + t] = si[t]; }
}

// ---------------- top-k stage 2: sort 4096 candidates ----------------
__global__ void k_top2() {
    __shared__ float sv[4096];
    __shared__ int   si[4096];
    int t = threadIdx.x;
    for (int i = t; i < 4096; i += 1024) { sv[i] = g_cand_val[i]; si[i] = g_cand_idx[i]; }
    __syncthreads();
    for (int k = 2; k <= 4096; k <<= 1) {
        for (int j = k >> 1; j > 0; j >>= 1) {
            for (int i = t; i < 4096; i += 1024) {
                int ixj = i ^ j;
                if (ixj > i) {
                    bool up = ((i & k) == 0);
                    float va = sv[i], vb = sv[ixj];
                    int ia = si[i], ib = si[ixj];
                    bool bba = before_pair(vb, ib, va, ia);
                    if (bba == up) { sv[i]=vb; sv[ixj]=va; si[i]=ib; si[ixj]=ia; }
                }
            }
            __syncthreads();
        }
    }
    if (t < TOP_K) g_topk[t] = si[t];
}

// ---------------- usage output ----------------
__global__ void k_usage_copy(const int* __restrict__ usage, float* __restrict__ outU) {
    int i = blockIdx.x * 256 + threadIdx.x;
    if (i < MEM_SIZE) outU[i] = (float)usage[i];
}
__global__ void k_usage_scatter(const int* __restrict__ usage, float* __restrict__ outU) {
    int t = threadIdx.x;
    if (t < TOP_K) {
        int idx = g_topk[t];
        outU[idx] = (float)(usage[idx] + 1);
    }
}

// ---------------- in_proj GEMM: xz[64][4096] = x @ W^T (x gathered from memory) -------
__global__ void k_xz(const float* __restrict__ mem, const float* __restrict__ W) {
    __shared__ float xs[64][33];
    __shared__ float ws[32][33];
    __shared__ int sidx[64];
    int tid = threadIdx.x;
    if (tid < 64) sidx[tid] = g_topk[tid];
    __syncthreads();
    int cbase = blockIdx.x * 32;
    float acc[4][2] = {{0.f,0.f},{0.f,0.f},{0.f,0.f},{0.f,0.f}};
    int tr = tid & 15, tc = tid >> 4;
    int kk = tid & 31, lr = tid >> 5;
    for (int kt = 0; kt < D_MODEL; kt += 32) {
        #pragma unroll
        for (int i = 0; i < 8; i++) {
            int l = lr + i * 8;
            xs[l][kk] = mem[(size_t)sidx[l] * D_MODEL + kt + kk];
        }
        #pragma unroll
        for (int i = 0; i < 4; i++) {
            int c = lr + i * 8;
            ws[c][kk] = W[(size_t)(cbase + c) * D_MODEL + kt + kk];
        }
        __syncthreads();
        #pragma unroll
        for (int p = 0; p < 32; p++) {
            float b0 = ws[tc*2][p], b1 = ws[tc*2+1][p];
            #pragma unroll
            for (int r = 0; r < 4; r++) {
                float a = xs[tr*4+r][p];
                acc[r][0] += a * b0;
                acc[r][1] += a * b1;
            }
        }
        __syncthreads();
    }
    #pragma unroll
    for (int r = 0; r < 4; r++)
        #pragma unroll
        for (int c = 0; c < 2; c++)
            g_xz[(tr*4+r) * (2*D_INNER) + cbase + tc*2 + c] = acc[r][c];
}

// ---------------- causal conv (width 4) + silu ----------------
__global__ void k_conv(const float* __restrict__ cw, const float* __restrict__ cb) {
    int i = blockIdx.x * 256 + threadIdx.x;          // i over 64*2048
    int l = i >> 11, e = i & (D_INNER - 1);
    float acc = cb[e];
    #pragma unroll
    for (int j = 0; j < D_CONV; j++) {
        int ls = l - (D_CONV - 1) + j;
        if (ls >= 0) acc += g_xz[ls * (2*D_INNER) + e] * cw[e * D_CONV + j];
    }
    g_uact[i] = acc / (1.f + expf(-acc));
}

// ---------------- x_proj: x_dbl[64][96] = u @ Wx^T ----------------
__global__ void k_xdbl(const float* __restrict__ Wx) {
    __shared__ float su[D_INNER];
    int l = blockIdx.x;
    int t = threadIdx.x, warp = t >> 5, lane = t & 31;
    for (int i = t; i < D_INNER; i += 256) su[i] = g_uact[l * D_INNER + i];
    __syncthreads();
    for (int o = warp; o < XPROJ_OUT; o += 8) {
        const float* wrow = Wx + (size_t)o * D_INNER;
        float a = 0.f;
        for (int k = lane; k < D_INNER; k += 32) a += su[k] * wrow[k];
        #pragma unroll
        for (int off = 16; off > 0; off >>= 1) a += __shfl_xor_sync(0xffffffffu, a, off);
        if (lane == 0) g_xdbl[l * XPROJ_OUT + o] = a;
    }
}

// ---------------- dt_proj + softplus -> delta[64][2048] ----------------
__global__ void k_delta(const float* __restrict__ Wd, const float* __restrict__ bd) {
    __shared__ float sdt[DT_RANK];
    int l = blockIdx.x >> 3;
    int ch = (blockIdx.x & 7) * 256;
    int t = threadIdx.x;
    if (t < DT_RANK) sdt[t] = g_xdbl[l * XPROJ_OUT + t];
    __syncthreads();
    int d = ch + t;
    float acc = bd[d];
    const float4* wrow = (const float4*)(Wd + (size_t)d * DT_RANK);
    #pragma unroll
    for (int r4 = 0; r4 < DT_RANK/4; r4++) {
        float4 w = wrow[r4];
        acc += sdt[r4*4]*w.x + sdt[r4*4+1]*w.y + sdt[r4*4+2]*w.z + sdt[r4*4+3]*w.w;
    }
    g_delta[l * D_INNER + d] = (acc > 25.f) ? acc : log1pf(expf(acc));
}

// ---------------- selective scan (only y[t=63] needed) + gate ----------------
__global__ void k_scan(const float* __restrict__ Alog, const float* __restrict__ Dp) {
    __shared__ float sB[L_SEQ][D_STATE];
    int t = threadIdx.x;
    int d = blockIdx.x * 16 + (t >> 4);
    int s = t & 15;
    for (int i = t; i < L_SEQ * D_STATE; i += 256) {
        int l = i >> 4, ss = i & 15;
        sB[l][ss] = g_xdbl[l * XPROJ_OUT + DT_RANK + ss];
    }
    __syncthreads();
    float A = -expf(Alog[d * D_STATE + s]);
    float h = 0.f;
    #pragma unroll 4
    for (int l = 0; l < L_SEQ; l++) {
        float dv = g_delta[l * D_INNER + d];
        float uv = g_uact[l * D_INNER + d];
        h = __expf(dv * A) * h + dv * sB[l][s] * uv;
    }
    float yp = h * g_xdbl[(L_SEQ-1) * XPROJ_OUT + DT_RANK + D_STATE + s];  // C at t=63
    #pragma unroll
    for (int off = 8; off > 0; off >>= 1) yp += __shfl_xor_sync(0xffffffffu, yp, off);
    if (s == 0) {
        float uv = g_uact[(L_SEQ-1) * D_INNER + d];
        float zv = g_xz[(L_SEQ-1) * (2*D_INNER) + D_INNER + d];
        float sz = zv / (1.f + expf(-zv));
        g_y[d] = (yp + uv * Dp[d]) * sz;
    }
}

// ---------------- out_proj matvec: ctx[1024] = Wo @ y ----------------
__global__ void k_outproj(const float* __restrict__ Wo) {
    __shared__ float sy[D_INNER];
    int t = threadIdx.x, warp = t >> 5, lane = t & 31;
    for (int i = t; i < D_INNER; i += 256) sy[i] = g_y[i];
    __syncthreads();
    int e = blockIdx.x * 8 + warp;
    const float4* wrow = (const float4*)(Wo + (size_t)e * D_INNER);
    float a = 0.f;
    #pragma unroll
    for (int i = 0; i < 16; i++) {
        int j = i * 32 + lane;
        float4 w = wrow[j];
        a += w.x*sy[j*4] + w.y*sy[j*4+1] + w.z*sy[j*4+2] + w.w*sy[j*4+3];
    }
    #pragma unroll
    for (int off = 16; off > 0; off >>= 1) a += __shfl_xor_sync(0xffffffffu, a, off);
    if (lane == 0) g_ctx[e] = a;
}

// ---------------- layernorm -> final output ----------------
__global__ void k_ln(const float* __restrict__ g, const float* __restrict__ b,
                     float* __restrict__ out) {
    __shared__ float red[1024];
    int t = threadIdx.x;
    float v = g_ctx[t];
    red[t] = v; __syncthreads();
    for (int o = 512; o > 0; o >>= 1) { if (t < o) red[t] += red[t+o]; __syncthreads(); }
    float mu = red[0] / (float)D_MODEL;
    __syncthreads();
    float dvv = v - mu;
    red[t] = dvv * dvv; __syncthreads();
    for (int o = 512; o > 0; o >>= 1) { if (t < o) red[t] += red[t+o]; __syncthreads(); }
    float var = red[0] / (float)D_MODEL;
    out[t] = dvv * rsqrtf(var + EPS_LN) * g[t] + b[t];
}

// ---------------- launch ----------------
extern "C" void kernel_launch(void* const* d_in, const int* in_sizes, int n_in,
                              void* d_out, int out_size) {
    const float* query    = (const float*)d_in[0];
    const float* memory   = (const float*)d_in[1];
    const int*   usage    = (const int*)  d_in[2];
    const float* in_proj  = (const float*)d_in[3];
    const float* conv_w   = (const float*)d_in[4];
    const float* conv_b   = (const float*)d_in[5];
    const float* x_proj   = (const float*)d_in[6];
    const float* dt_proj  = (const float*)d_in[7];
    const float* dt_b     = (const float*)d_in[8];
    const float* A_log    = (const float*)d_in[9];
    const float* Dp       = (const float*)d_in[10];
    const float* out_proj = (const float*)d_in[11];
    const float* ln_g     = (const float*)d_in[12];
    const float* ln_b     = (const float*)d_in[13];

    float* outF = (float*)d_out;
    bool has_usage = (out_size >= D_MODEL + MEM_SIZE);
    float* outU = outF + D_MODEL;

    k_qnorm<<<1, 256>>>(query);
    k_sims<<<MEM_SIZE/128, 256>>>(memory, query);
    k_top1<<<64, 1024>>>();
    k_top2<<<1, 1024>>>();
    if (has_usage) {
        k_usage_copy<<<MEM_SIZE/256, 256>>>(usage, outU);
        k_usage_scatter<<<1, 64>>>(usage, outU);
    }
    k_xz<<<128, 256>>>(memory, in_proj);
    k_conv<<<(L_SEQ*D_INNER)/256, 256>>>(conv_w, conv_b);
    k_xdbl<<<L_SEQ, 256>>>(x_proj);
    k_delta<<<L_SEQ*8, 256>>>(dt_proj, dt_b);
    k_scan<<<D_INNER/16, 256>>>(A_log, Dp);
    k_outproj<<<D_MODEL/8, 256>>>(out_proj);
    k_ln<<<1, 1024>>>(ln_g, ln_b, outF);
}

// round 3
// speedup vs baseline: 1.1117x; 1.1117x over previous
#include <cuda_runtime.h>
#include <cuda_bf16.h>
#include <math.h>

#define D_MODEL   1024
#define MEM_SIZE  131072
#define TOP_K     64
#define D_STATE   16
#define D_CONV    4
#define D_INNER   2048
#define DT_RANK   64
#define XPROJ_OUT (DT_RANK + 2*D_STATE)   // 96
#define L_SEQ     64
#define EPS_COS   1e-8f
#define EPS_LN    1e-5f
#define CAND_CAP  4096

// ---------------- scratch (no allocations allowed) ----------------
__device__ float g_sims[MEM_SIZE];
__device__ unsigned int g_h1[256], g_h2[256], g_h3[256];
__device__ int g_b1, g_above1, g_p16, g_above2, g_p24;
__device__ unsigned int g_ccnt;
__device__ float g_cval[CAND_CAP];
__device__ int   g_cidx[CAND_CAP];
__device__ int   g_topk[TOP_K];
__device__ float g_qn[1];
__device__ float g_xz[L_SEQ * 2 * D_INNER];     // 64 x 4096
__device__ float g_uact[L_SEQ * D_INNER];       // 64 x 2048 (post conv+silu)
__device__ float g_xdbl[L_SEQ * XPROJ_OUT];     // 64 x 96
__device__ float g_delta[L_SEQ * D_INNER];      // 64 x 2048
__device__ float g_y[D_INNER];                  // gated y at t=63
__device__ float g_ctx[D_MODEL];                // out_proj result

__device__ __forceinline__ unsigned int fkey(float v) {
    unsigned int u = __float_as_uint(v);
    return (u & 0x80000000u) ? ~u : (u | 0x80000000u);
}
__device__ __forceinline__ bool before_pair(float va, int ia, float vb, int ib) {
    return (va > vb) || (va == vb && ia < ib);   // value desc, index asc
}

// ---------------- query norm + zero all select state ----------------
__global__ void k_qnorm(const float* __restrict__ q) {
    __shared__ float red[256];
    int t = threadIdx.x;
    // zero histograms + counter (re-zeroed every graph replay)
    g_h1[t] = 0u; g_h2[t] = 0u; g_h3[t] = 0u;
    if (t == 0) g_ccnt = 0u;
    float s = 0.f;
    for (int i = t; i < D_MODEL; i += 256) { float v = q[i]; s += v*v; }
    red[t] = s; __syncthreads();
    for (int o = 128; o > 0; o >>= 1) { if (t < o) red[t] += red[t+o]; __syncthreads(); }
    if (t == 0) g_qn[0] = sqrtf(red[0]);
}

// ---------------- fused dot + norm + cosine sim + top-8-bit histogram ----------------
__global__ void k_sims(const float* __restrict__ mem, const float* __restrict__ q) {
    __shared__ float sq[D_MODEL];
    __shared__ unsigned int sh[256];
    int t = threadIdx.x;
    for (int i = t; i < D_MODEL; i += 256) sq[i] = q[i];
    if (t < 256) sh[t] = 0u;
    __syncthreads();
    int warp = t >> 5, lane = t & 31;
    float qn = g_qn[0];
    int rbase = blockIdx.x * 128 + warp * 16;
    for (int rr = 0; rr < 16; rr++) {
        int r = rbase + rr;
        const float4* row = (const float4*)(mem + (size_t)r * D_MODEL);
        float dot = 0.f, nr = 0.f;
        #pragma unroll
        for (int i = 0; i < 8; i++) {
            int j = i * 32 + lane;
            float4 m = row[j];
            float4 qv = *(const float4*)&sq[j*4];
            dot += m.x*qv.x + m.y*qv.y + m.z*qv.z + m.w*qv.w;
            nr  += m.x*m.x + m.y*m.y + m.z*m.z + m.w*m.w;
        }
        #pragma unroll
        for (int o = 16; o > 0; o >>= 1) {
            dot += __shfl_xor_sync(0xffffffffu, dot, o);
            nr  += __shfl_xor_sync(0xffffffffu, nr,  o);
        }
        if (lane == 0) {
            float s = dot / fmaxf(sqrtf(nr) * qn, EPS_COS);
            g_sims[r] = s;
            atomicAdd(&sh[fkey(s) >> 24], 1u);
        }
    }
    __syncthreads();
    if (t < 256 && sh[t]) atomicAdd(&g_h1[t], sh[t]);
}

// ---------------- radix-select scans (1-thread; tiny) ----------------
__global__ void k_sel1() {
    if (threadIdx.x == 0) {
        int cum = 0, b = 0, above = 0;
        for (int i = 255; i >= 0; i--) {
            int c = (int)g_h1[i];
            if (cum + c >= TOP_K) { b = i; above = cum; break; }
            cum += c;
        }
        g_b1 = b; g_above1 = above;
    }
}
__global__ void k_hist2() {
    int i = blockIdx.x * 256 + threadIdx.x;
    unsigned int k = fkey(g_sims[i]);
    if ((int)(k >> 24) == g_b1) atomicAdd(&g_h2[(k >> 16) & 0xFF], 1u);
}
__global__ void k_sel2() {
    if (threadIdx.x == 0) {
        int need = TOP_K - g_above1;
        int cum = 0, b = 0, above = 0;
        for (int i = 255; i >= 0; i--) {
            int c = (int)g_h2[i];
            if (cum + c >= need) { b = i; above = cum; break; }
            cum += c;
        }
        g_p16 = (g_b1 << 8) | b;
        g_above2 = g_above1 + above;
    }
}
__global__ void k_hist3() {
    int i = blockIdx.x * 256 + threadIdx.x;
    unsigned int k = fkey(g_sims[i]);
    if ((int)(k >> 16) == g_p16) atomicAdd(&g_h3[(k >> 8) & 0xFF], 1u);
}
__global__ void k_sel3() {
    if (threadIdx.x == 0) {
        int need = TOP_K - g_above2;
        int cum = 0, b = 0;
        for (int i = 255; i >= 0; i--) {
            int c = (int)g_h3[i];
            if (cum + c >= need) { b = i; break; }
            cum += c;
        }
        g_p24 = (g_p16 << 8) | b;
    }
}
__global__ void k_collect() {
    int i = blockIdx.x * 256 + threadIdx.x;
    float v = g_sims[i];
    unsigned int k = fkey(v);
    if ((int)(k >> 8) >= g_p24) {
        unsigned int p = atomicAdd(&g_ccnt, 1u);
        if (p < CAND_CAP) { g_cval[p] = v; g_cidx[p] = i; }
    }
}

// ---------------- final: sort C candidates, emit topk + usage scatter ----------------
__global__ void k_final(const int* __restrict__ usage, float* __restrict__ outU, int hasU) {
    __shared__ float sv[CAND_CAP];
    __shared__ int   si[CAND_CAP];
    int t = threadIdx.x;
    int C = (int)min(g_ccnt, (unsigned int)CAND_CAP);
    int n = TOP_K;
    while (n < C) n <<= 1;
    const float NEGINF = __int_as_float(0xff800000);
    for (int i = t; i < n; i += 256) {
        if (i < C) { sv[i] = g_cval[i]; si[i] = g_cidx[i]; }
        else       { sv[i] = NEGINF;    si[i] = 0x7fffffff; }
    }
    __syncthreads();
    for (int k = 2; k <= n; k <<= 1) {
        for (int j = k >> 1; j > 0; j >>= 1) {
            for (int i = t; i < n; i += 256) {
                int ixj = i ^ j;
                if (ixj > i) {
                    bool up = ((i & k) == 0);
                    float va = sv[i], vb = sv[ixj];
                    int ia = si[i], ib = si[ixj];
                    bool bba = before_pair(vb, ib, va, ia);
                    if (bba == up) { sv[i]=vb; sv[ixj]=va; si[i]=ib; si[ixj]=ia; }
                }
            }
            __syncthreads();
        }
    }
    if (t < TOP_K) {
        int idx = si[t];
        g_topk[t] = idx;
        if (hasU) outU[idx] = (float)(usage[idx] + 1);
    }
}

// ---------------- usage output (full copy; scatter overwrites in k_final) --------
__global__ void k_usage_copy(const int* __restrict__ usage, float* __restrict__ outU) {
    int i = blockIdx.x * 256 + threadIdx.x;
    if (i < MEM_SIZE) outU[i] = (float)usage[i];
}

// ---------------- in_proj GEMM: xz[64][4096] = x @ W^T (x gathered from memory) -------
__global__ void k_xz(const float* __restrict__ mem, const float* __restrict__ W) {
    __shared__ float xs[64][33];
    __shared__ float ws[32][33];
    __shared__ int sidx[64];
    int tid = threadIdx.x;
    if (tid < 64) sidx[tid] = g_topk[tid];
    __syncthreads();
    int cbase = blockIdx.x * 32;
    float acc[4][2] = {{0.f,0.f},{0.f,0.f},{0.f,0.f},{0.f,0.f}};
    int tr = tid & 15, tc = tid >> 4;
    int kk = tid & 31, lr = tid >> 5;
    for (int kt = 0; kt < D_MODEL; kt += 32) {
        #pragma unroll
        for (int i = 0; i < 8; i++) {
            int l = lr + i * 8;
            xs[l][kk] = mem[(size_t)sidx[l] * D_MODEL + kt + kk];
        }
        #pragma unroll
        for (int i = 0; i < 4; i++) {
            int c = lr + i * 8;
            ws[c][kk] = W[(size_t)(cbase + c) * D_MODEL + kt + kk];
        }
        __syncthreads();
        #pragma unroll
        for (int p = 0; p < 32; p++) {
            float b0 = ws[tc*2][p], b1 = ws[tc*2+1][p];
            #pragma unroll
            for (int r = 0; r < 4; r++) {
                float a = xs[tr*4+r][p];
                acc[r][0] += a * b0;
                acc[r][1] += a * b1;
            }
        }
        __syncthreads();
    }
    #pragma unroll
    for (int r = 0; r < 4; r++)
        #pragma unroll
        for (int c = 0; c < 2; c++)
            g_xz[(tr*4+r) * (2*D_INNER) + cbase + tc*2 + c] = acc[r][c];
}

// ---------------- causal conv (width 4) + silu ----------------
__global__ void k_conv(const float* __restrict__ cw, const float* __restrict__ cb) {
    int i = blockIdx.x * 256 + threadIdx.x;          // i over 64*2048
    int l = i >> 11, e = i & (D_INNER - 1);
    float acc = cb[e];
    #pragma unroll
    for (int j = 0; j < D_CONV; j++) {
        int ls = l - (D_CONV - 1) + j;
        if (ls >= 0) acc += g_xz[ls * (2*D_INNER) + e] * cw[e * D_CONV + j];
    }
    g_uact[i] = acc / (1.f + expf(-acc));
}

// ---------------- x_proj: x_dbl[64][96] = u @ Wx^T ----------------
__global__ void k_xdbl(const float* __restrict__ Wx) {
    __shared__ float su[D_INNER];
    int l = blockIdx.x;
    int t = threadIdx.x, warp = t >> 5, lane = t & 31;
    for (int i = t; i < D_INNER; i += 256) su[i] = g_uact[l * D_INNER + i];
    __syncthreads();
    for (int o = warp; o < XPROJ_OUT; o += 8) {
        const float* wrow = Wx + (size_t)o * D_INNER;
        float a = 0.f;
        for (int k = lane; k < D_INNER; k += 32) a += su[k] * wrow[k];
        #pragma unroll
        for (int off = 16; off > 0; off >>= 1) a += __shfl_xor_sync(0xffffffffu, a, off);
        if (lane == 0) g_xdbl[l * XPROJ_OUT + o] = a;
    }
}

// ---------------- dt_proj + softplus -> delta[64][2048] ----------------
__global__ void k_delta(const float* __restrict__ Wd, const float* __restrict__ bd) {
    __shared__ float sdt[DT_RANK];
    int l = blockIdx.x >> 3;
    int ch = (blockIdx.x & 7) * 256;
    int t = threadIdx.x;
    if (t < DT_RANK) sdt[t] = g_xdbl[l * XPROJ_OUT + t];
    __syncthreads();
    int d = ch + t;
    float acc = bd[d];
    const float4* wrow = (const float4*)(Wd + (size_t)d * DT_RANK);
    #pragma unroll
    for (int r4 = 0; r4 < DT_RANK/4; r4++) {
        float4 w = wrow[r4];
        acc += sdt[r4*4]*w.x + sdt[r4*4+1]*w.y + sdt[r4*4+2]*w.z + sdt[r4*4+3]*w.w;
    }
    g_delta[l * D_INNER + d] = (acc > 25.f) ? acc : log1pf(expf(acc));
}

// ---------------- selective scan (only y[t=63] needed) + gate ----------------
__global__ void k_scan(const float* __restrict__ Alog, const float* __restrict__ Dp) {
    __shared__ float sB[L_SEQ][D_STATE];
    int t = threadIdx.x;
    int d = blockIdx.x * 16 + (t >> 4);
    int s = t & 15;
    for (int i = t; i < L_SEQ * D_STATE; i += 256) {
        int l = i >> 4, ss = i & 15;
        sB[l][ss] = g_xdbl[l * XPROJ_OUT + DT_RANK + ss];
    }
    __syncthreads();
    float A = -expf(Alog[d * D_STATE + s]);
    float h = 0.f;
    #pragma unroll 4
    for (int l = 0; l < L_SEQ; l++) {
        float dv = g_delta[l * D_INNER + d];
        float uv = g_uact[l * D_INNER + d];
        h = __expf(dv * A) * h + dv * sB[l][s] * uv;
    }
    float yp = h * g_xdbl[(L_SEQ-1) * XPROJ_OUT + DT_RANK + D_STATE + s];  // C at t=63
    #pragma unroll
    for (int off = 8; off > 0; off >>= 1) yp += __shfl_xor_sync(0xffffffffu, yp, off);
    if (s == 0) {
        float uv = g_uact[(L_SEQ-1) * D_INNER + d];
        float zv = g_xz[(L_SEQ-1) * (2*D_INNER) + D_INNER + d];
        float sz = zv / (1.f + expf(-zv));
        g_y[d] = (yp + uv * Dp[d]) * sz;
    }
}

// ---------------- out_proj matvec: ctx[1024] = Wo @ y ----------------
__global__ void k_outproj(const float* __restrict__ Wo) {
    __shared__ float sy[D_INNER];
    int t = threadIdx.x, warp = t >> 5, lane = t & 31;
    for (int i = t; i < D_INNER; i += 256) sy[i] = g_y[i];
    __syncthreads();
    int e = blockIdx.x * 8 + warp;
    const float4* wrow = (const float4*)(Wo + (size_t)e * D_INNER);
    float a = 0.f;
    #pragma unroll
    for (int i = 0; i < 16; i++) {
        int j = i * 32 + lane;
        float4 w = wrow[j];
        a += w.x*sy[j*4] + w.y*sy[j*4+1] + w.z*sy[j*4+2] + w.w*sy[j*4+3];
    }
    #pragma unroll
    for (int off = 16; off > 0; off >>= 1) a += __shfl_xor_sync(0xffffffffu, a, off);
    if (lane == 0) g_ctx[e] = a;
}

// ---------------- layernorm -> final output ----------------
__global__ void k_ln(const float* __restrict__ g, const float* __restrict__ b,
                     float* __restrict__ out) {
    __shared__ float red[1024];
    int t = threadIdx.x;
    float v = g_ctx[t];
    red[t] = v; __syncthreads();
    for (int o = 512; o > 0; o >>= 1) { if (t < o) red[t] += red[t+o]; __syncthreads(); }
    float mu = red[0] / (float)D_MODEL;
    __syncthreads();
    float dvv = v - mu;
    red[t] = dvv * dvv; __syncthreads();
    for (int o = 512; o > 0; o >>= 1) { if (t < o) red[t] += red[t+o]; __syncthreads(); }
    float var = red[0] / (float)D_MODEL;
    out[t] = dvv * rsqrtf(var + EPS_LN) * g[t] + b[t];
}

// ---------------- launch ----------------
extern "C" void kernel_launch(void* const* d_in, const int* in_sizes, int n_in,
                              void* d_out, int out_size) {
    const float* query    = (const float*)d_in[0];
    const float* memory   = (const float*)d_in[1];
    const int*   usage    = (const int*)  d_in[2];
    const float* in_proj  = (const float*)d_in[3];
    const float* conv_w   = (const float*)d_in[4];
    const float* conv_b   = (const float*)d_in[5];
    const float* x_proj   = (const float*)d_in[6];
    const float* dt_proj  = (const float*)d_in[7];
    const float* dt_b     = (const float*)d_in[8];
    const float* A_log    = (const float*)d_in[9];
    const float* Dp       = (const float*)d_in[10];
    const float* out_proj = (const float*)d_in[11];
    const float* ln_g     = (const float*)d_in[12];
    const float* ln_b     = (const float*)d_in[13];

    float* outF = (float*)d_out;
    bool has_usage = (out_size >= D_MODEL + MEM_SIZE);
    float* outU = outF + D_MODEL;

    k_qnorm<<<1, 256>>>(query);
    k_sims<<<MEM_SIZE/128, 256>>>(memory, query);
    k_sel1<<<1, 32>>>();
    k_hist2<<<MEM_SIZE/256, 256>>>();
    k_sel2<<<1, 32>>>();
    k_hist3<<<MEM_SIZE/256, 256>>>();
    k_sel3<<<1, 32>>>();
    k_collect<<<MEM_SIZE/256, 256>>>();
    if (has_usage) k_usage_copy<<<MEM_SIZE/256, 256>>>(usage, outU);
    k_final<<<1, 256>>>(usage, has_usage ? outU : (float*)nullptr, has_usage ? 1 : 0);
    k_xz<<<128, 256>>>(memory, in_proj);
    k_conv<<<(L_SEQ*D_INNER)/256, 256>>>(conv_w, conv_b);
    k_xdbl<<<L_SEQ, 256>>>(x_proj);
    k_delta<<<L_SEQ*8, 256>>>(dt_proj, dt_b);
    k_scan<<<D_INNER/16, 256>>>(A_log, Dp);
    k_outproj<<<D_MODEL/8, 256>>>(out_proj);
    k_ln<<<1, 1024>>>(ln_g, ln_b, outF);
}